// round 8
// baseline (speedup 1.0000x reference)
#include <cuda_runtime.h>
#include <cuda_fp16.h>
#include <math.h>

// Problem constants
#define Bsz   128
#define Nn    512
#define GJ    1536          // 3*512 gate columns
#define MROWS (Bsz*Nn)      // 65536
#define NCTA  148           // persistent grid (1 CTA/SM guaranteed resident)
#define NWELEM 786432       // elements per weight matrix (1536*512)

// ---------------- device scratch (allocation-free) ---------------------------
__device__ float  g_Ubuf[(size_t)MROWS * GJ];   // emb@ul^T + bias
__device__ float  g_LW  [(size_t)MROWS * GJ];   // emb@wl^T
__device__ float  g_rlin[(size_t)MROWS * GJ];   // ph@ur^T
__device__ float  g_cbuf[(size_t)MROWS * 512];  // cell state
__device__ float  g_pooled[(size_t)MROWS * 24]; // pooled bilinear
__device__ __half g_embH[(size_t)MROWS * 512];  // fp16 emb
__device__ __half g_hH  [(size_t)MROWS * 512];  // fp16 h (scan A operand)
__device__ __half g_wH  [4 * NWELEM];           // fp16 weights: ul, wl, wr, ur
__device__ __half g_zeroH[512];                 // zero row

__device__ int g_level[MROWS];
__device__ int g_lcount[512];
__device__ int g_lstart[513];
__device__ int g_lcur[512];
__device__ int g_nodelist[MROWS];
__device__ int g_maxlev;

__device__ unsigned g_gcnt = 0;
__device__ unsigned g_ggen = 0;

// ---------------- mma / cp.async helpers -------------------------------------
__device__ __forceinline__ void mma16(float* c, const unsigned* a, const unsigned* b) {
    asm volatile(
        "mma.sync.aligned.m16n8k16.row.col.f32.f16.f16.f32 "
        "{%0,%1,%2,%3},{%4,%5,%6,%7},{%8,%9},{%0,%1,%2,%3};"
        : "+f"(c[0]), "+f"(c[1]), "+f"(c[2]), "+f"(c[3])
        : "r"(a[0]), "r"(a[1]), "r"(a[2]), "r"(a[3]), "r"(b[0]), "r"(b[1]));
}
__device__ __forceinline__ void cpa16(unsigned dst, const void* src) {
    asm volatile("cp.async.cg.shared.global [%0], [%1], 16;" :: "r"(dst), "l"(src));
}
#define CP_COMMIT() asm volatile("cp.async.commit_group;")
#define CP_WAIT1()  asm volatile("cp.async.wait_group 1;")

__device__ __forceinline__ unsigned ldh2(const __half* p) {
    return *(const unsigned*)p;
}

// ---------------- fp32 -> fp16 conversion (one pass, all GEMM inputs) --------
__global__ void conv_all(const float* __restrict__ emb,
                         const float* __restrict__ ul, const float* __restrict__ wl,
                         const float* __restrict__ wr, const float* __restrict__ ur)
{
    const size_t NE = (size_t)MROWS * 512 / 4;   // emb quarters
    const size_t NW = NWELEM / 4;                // weight quarters
    size_t i = (size_t)blockIdx.x * 256 + threadIdx.x;
    const float* src; __half* dst; size_t q;
    if (i < NE) { src = emb; dst = g_embH; q = i; }
    else {
        size_t j = i - NE;
        if (j >= 4 * NW) return;
        int w = (int)(j / NW); q = j % NW;
        src = (w == 0) ? ul : (w == 1) ? wl : (w == 2) ? wr : ur;
        dst = g_wH + (size_t)w * NWELEM;
    }
    float4 v = ((const float4*)src)[q];
    __half2* d2 = (__half2*)(dst + q * 4);
    d2[0] = __floats2half2_rn(v.x, v.y);
    d2[1] = __floats2half2_rn(v.z, v.w);
}

// ---------------- level metadata --------------------------------------------
__global__ void build_depth(const int* __restrict__ nc) {
    __shared__ int spar[512];
    __shared__ unsigned short dep[512];
    const int b = blockIdx.x;
    for (int t = threadIdx.x; t < 512; t += 32) spar[t] = nc[b * 512 + t];
    __syncthreads();
    if (threadIdx.x == 0) {
        for (int t = 0; t < 512; t++) {
            int par = spar[t];
            dep[t] = (t > 0 && par < t) ? (unsigned short)(dep[par] + 1) : 0;
        }
    }
    __syncthreads();
    for (int t = threadIdx.x; t < 512; t += 32) {
        int lv = dep[t];
        g_level[b * 512 + t] = lv;
        atomicAdd(&g_lcount[lv], 1);
    }
}

// ---------------- precompute GEMM (fp16 mma, 512 threads, 16 warps) ----------
// C[M x 1536] = embH @ W^T (+bias). BM=128, BN=256, BK=32, 3 stages.
__global__ __launch_bounds__(512, 1) void gemm_pre(const float* __restrict__ bias)
{
    __shared__ __align__(16) __half HSM[46080];  // 3 x (A 128x40 + B 256x40)

    const int sel = blockIdx.z;
    float* C = sel ? g_LW : g_Ubuf;

    const int tid = threadIdx.x, lane = tid & 31, warp = tid >> 5;
    const int wm = (warp & 1) * 64, wn = (warp >> 1) * 32;
    const int g = lane >> 2, cc2 = (lane & 3) * 2, cc = lane & 3;
    const int r0 = blockIdx.y * 128, c0 = blockIdx.x * 256;
    const __half* Ab = g_embH + (size_t)r0 * 512;
    const __half* Wb = g_wH + (size_t)sel * NWELEM + (size_t)c0 * 512;

    const int ar = tid >> 2, ac = (tid & 3) * 8;    // A: 1 cpa16
    const int br = tid >> 1, bc = (tid & 1) * 16;   // B: 2 cpa16
    const unsigned sb = (unsigned)__cvta_generic_to_shared(HSM);

    auto issue = [&](int st, int kt) {
        unsigned ad = sb + (unsigned)(st * 15360 + ar * 40 + ac) * 2u;
        cpa16(ad, Ab + (size_t)ar * 512 + kt * 32 + ac);
        const __half* bs_ = Wb + (size_t)br * 512 + kt * 32 + bc;
        unsigned bd = sb + (unsigned)(st * 15360 + 5120 + br * 40 + bc) * 2u;
        cpa16(bd, bs_); cpa16(bd + 16, bs_ + 8);
    };

    issue(0, 0); CP_COMMIT();
    issue(1, 1); CP_COMMIT();

    float acc[4][4][4];
    #pragma unroll
    for (int mt = 0; mt < 4; mt++)
        #pragma unroll
        for (int nt = 0; nt < 4; nt++)
            #pragma unroll
            for (int j = 0; j < 4; j++) acc[mt][nt][j] = 0.f;

    for (int kt = 0; kt < 16; kt++) {
        CP_WAIT1();
        __syncthreads();
        if (kt + 2 < 16) issue((kt + 2) % 3, kt + 2);
        CP_COMMIT();

        const __half* As = HSM + (kt % 3) * 15360;
        const __half* Bs = As + 5120;
        #pragma unroll
        for (int ks = 0; ks < 2; ks++) {
            const int k0 = ks * 16;
            unsigned af[4][4], bf[4][2];
            #pragma unroll
            for (int mt = 0; mt < 4; mt++) {
                const int rb = wm + mt * 16 + g;
                af[mt][0] = ldh2(&As[rb * 40 + k0 + cc2]);
                af[mt][1] = ldh2(&As[(rb + 8) * 40 + k0 + cc2]);
                af[mt][2] = ldh2(&As[rb * 40 + k0 + cc2 + 8]);
                af[mt][3] = ldh2(&As[(rb + 8) * 40 + k0 + cc2 + 8]);
            }
            #pragma unroll
            for (int nt = 0; nt < 4; nt++) {
                const int nb = wn + nt * 8 + g;
                bf[nt][0] = ldh2(&Bs[nb * 40 + k0 + cc2]);
                bf[nt][1] = ldh2(&Bs[nb * 40 + k0 + cc2 + 8]);
            }
            #pragma unroll
            for (int mt = 0; mt < 4; mt++)
                #pragma unroll
                for (int nt = 0; nt < 4; nt++) mma16(acc[mt][nt], af[mt], bf[nt]);
        }
    }
    __syncthreads();

    // epilogue: 4 passes of 64 cols staged through smem (alias as float)
    float* stage = (float*)HSM;   // 128*68 floats
    const int rr = tid >> 2, q = tid & 3;
    #pragma unroll
    for (int p = 0; p < 4; p++) {
        if ((warp >> 1) == 2 * p || (warp >> 1) == 2 * p + 1) {
            const int colbase = wn - p * 64;   // 0 or 32
            #pragma unroll
            for (int mt = 0; mt < 4; mt++)
                #pragma unroll
                for (int nt = 0; nt < 4; nt++) {
                    const int row = wm + mt * 16 + g, col = colbase + nt * 8 + cc * 2;
                    *(float2*)&stage[row * 68 + col]       = make_float2(acc[mt][nt][0], acc[mt][nt][1]);
                    *(float2*)&stage[(row + 8) * 68 + col] = make_float2(acc[mt][nt][2], acc[mt][nt][3]);
                }
        }
        __syncthreads();
        const int cg = c0 + p * 64 + q * 16;
        #pragma unroll
        for (int i = 0; i < 4; i++) {
            float4 v = *(float4*)&stage[rr * 68 + q * 16 + i * 4];
            if (sel == 0) {
                v.x += bias[cg + i * 4];     v.y += bias[cg + i * 4 + 1];
                v.z += bias[cg + i * 4 + 2]; v.w += bias[cg + i * 4 + 3];
            }
            *(float4*)(C + (size_t)(r0 + rr) * GJ + cg + i * 4) = v;
        }
        __syncthreads();
    }
}

// ---------------- persistent level-scan kernel (fp16 mma, 512 threads) -------
// BM=128, BN=256, BK=32, 3 stages, 16 warps of 64x32.
__global__ __launch_bounds__(512, 1) void scan_levels(
    float* __restrict__ out,
    const int* __restrict__ nc,
    const float* __restrict__ wo)    // (3, 512, 8)
{
    __shared__ __align__(16) __half HSM[46080];
    __shared__ int rowoff[128];
    __shared__ int rowgid[128];

    const int tid = threadIdx.x, lane = tid & 31, warp = tid >> 5;
    const int wm = (warp & 1) * 64, wn = (warp >> 1) * 32;
    const int g = lane >> 2, cc2 = (lane & 3) * 2, cc = lane & 3;
    const int ar = tid >> 2, ac = (tid & 3) * 8;
    const int br = tid >> 1, bc = (tid & 1) * 16;
    const unsigned ncta = gridDim.x;
    const unsigned sb = (unsigned)__cvta_generic_to_shared(HSM);
    const __half* wrH = g_wH + 2 * (size_t)NWELEM;
    const __half* urH = g_wH + 3 * (size_t)NWELEM;

    const unsigned base = *(volatile unsigned*)&g_ggen;
    unsigned nbar = 0;

    // grid barrier helper (macro-style via lambda)
    auto gridbar = [&]() {
        nbar++;
        __syncthreads();
        if (tid == 0) {
            __threadfence();
            unsigned arrived = atomicAdd(&g_gcnt, 1u);
            if (arrived == ncta - 1u) {
                g_gcnt = 0;
                __threadfence();
                atomicAdd(&g_ggen, 1u);
            } else {
                while ((*(volatile unsigned*)&g_ggen) - base < nbar) { }
            }
            __threadfence();
        }
        __syncthreads();
    };

    // ---- prologue: prefix levels (CTA 0) then scatter ----
    if (blockIdx.x == 0 && tid == 0) {
        int sum = 0, mx = 0;
        for (int l = 0; l < 512; l++) {
            g_lstart[l] = sum;
            g_lcur[l]   = sum;
            int cnt = g_lcount[l];
            if (cnt > 0) mx = l;
            sum += cnt;
            g_lcount[l] = 0;
        }
        g_lstart[512] = sum;
        g_maxlev = mx;
    }
    gridbar();
    {
        int i = blockIdx.x * 512 + tid;
        if (i < MROWS) {
            int pos = atomicAdd(&g_lcur[g_level[i]], 1);
            g_nodelist[pos] = i;
        }
    }
    gridbar();
    const int maxlev = *(volatile int*)&g_maxlev;

    for (int lev = 0; lev <= maxlev; lev++) {
        const int s = g_lstart[lev];
        const int R = g_lstart[lev + 1] - s;
        const int nrb = (R + 127) >> 7;
        const int units = nrb * 12;   // 3072/256 col blocks

        // ---------------- phase 1: recurrent GEMM + pooling ----------------
        for (int u = blockIdx.x; u < units; u += ncta) {
            const int rb = u / 12;
            const int cb = u - rb * 12;
            const int row0 = rb << 7;

            if (tid < 128) {
                int r = row0 + tid;
                int off = -1, gid = -1;
                if (r < R) {
                    gid = g_nodelist[s + r];
                    int b = gid >> 9, t = gid & 511;
                    int par = nc[(b << 9) + t];
                    if (t > 0 && par < t) off = ((b << 9) + par) << 9;
                }
                rowgid[tid] = gid;
                rowoff[tid] = off;
            }
            __syncthreads();

            const int aoff = rowoff[ar];
            const __half* abase = (aoff >= 0) ? (g_hH + (size_t)aoff) : g_zeroH;
            const __half* Wb = (cb < 6)
                ? (wrH + (size_t)cb * 131072)
                : (urH + (size_t)(cb - 6) * 131072);
            const __half* brow_ptr = Wb + (size_t)br * 512;

            auto issue = [&](int st, int kt) {
                unsigned ad = sb + (unsigned)(st * 15360 + ar * 40 + ac) * 2u;
                cpa16(ad, abase + kt * 32 + ac);
                const __half* bs_ = brow_ptr + kt * 32 + bc;
                unsigned bd = sb + (unsigned)(st * 15360 + 5120 + br * 40 + bc) * 2u;
                cpa16(bd, bs_); cpa16(bd + 16, bs_ + 8);
            };

            issue(0, 0); CP_COMMIT();
            issue(1, 1); CP_COMMIT();

            float acc[4][4][4];
            #pragma unroll
            for (int mt = 0; mt < 4; mt++)
                #pragma unroll
                for (int nt = 0; nt < 4; nt++)
                    #pragma unroll
                    for (int j = 0; j < 4; j++) acc[mt][nt][j] = 0.f;

            for (int kt = 0; kt < 16; kt++) {
                CP_WAIT1();
                __syncthreads();
                if (kt + 2 < 16) issue((kt + 2) % 3, kt + 2);
                CP_COMMIT();

                const __half* As = HSM + (kt % 3) * 15360;
                const __half* Bs = As + 5120;
                #pragma unroll
                for (int ks = 0; ks < 2; ks++) {
                    const int k0 = ks * 16;
                    unsigned af[4][4], bf[4][2];
                    #pragma unroll
                    for (int mt = 0; mt < 4; mt++) {
                        const int rb2 = wm + mt * 16 + g;
                        af[mt][0] = ldh2(&As[rb2 * 40 + k0 + cc2]);
                        af[mt][1] = ldh2(&As[(rb2 + 8) * 40 + k0 + cc2]);
                        af[mt][2] = ldh2(&As[rb2 * 40 + k0 + cc2 + 8]);
                        af[mt][3] = ldh2(&As[(rb2 + 8) * 40 + k0 + cc2 + 8]);
                    }
                    #pragma unroll
                    for (int nt = 0; nt < 4; nt++) {
                        const int nb2 = wn + nt * 8 + g;
                        bf[nt][0] = ldh2(&Bs[nb2 * 40 + k0 + cc2]);
                        bf[nt][1] = ldh2(&Bs[nb2 * 40 + k0 + cc2 + 8]);
                    }
                    #pragma unroll
                    for (int mt = 0; mt < 4; mt++)
                        #pragma unroll
                        for (int nt = 0; nt < 4; nt++) mma16(acc[mt][nt], af[mt], bf[nt]);
                }
            }
            __syncthreads();

            // epilogue: 4 passes of 64 cols through stage
            float* stage = (float*)HSM;
            const int rr = tid >> 2, q = tid & 3;
            const int gid = rowgid[rr];
            #pragma unroll
            for (int p = 0; p < 4; p++) {
                if ((warp >> 1) == 2 * p || (warp >> 1) == 2 * p + 1) {
                    const int colbase = wn - p * 64;
                    #pragma unroll
                    for (int mt = 0; mt < 4; mt++)
                        #pragma unroll
                        for (int nt = 0; nt < 4; nt++) {
                            const int row = wm + mt * 16 + g, col = colbase + nt * 8 + cc * 2;
                            *(float2*)&stage[row * 68 + col]       = make_float2(acc[mt][nt][0], acc[mt][nt][1]);
                            *(float2*)&stage[(row + 8) * 68 + col] = make_float2(acc[mt][nt][2], acc[mt][nt][3]);
                        }
                }
                __syncthreads();

                if (cb < 6) {
                    // bilinear pooling: this 64-col slab = pool group cb*4+p
                    float v = 0.f;
                    if (gid >= 0) {
                        const float* lwp = g_LW + (size_t)gid * GJ + (cb << 8) + p * 64 + q * 16;
                        #pragma unroll
                        for (int i = 0; i < 4; i++) {
                            float4 l4 = *(const float4*)(lwp + i * 4);
                            float4 c4 = *(float4*)&stage[rr * 68 + q * 16 + i * 4];
                            v += c4.x * l4.x + c4.y * l4.y + c4.z * l4.z + c4.w * l4.w;
                        }
                    }
                    v += __shfl_xor_sync(0xffffffffu, v, 1);
                    v += __shfl_xor_sync(0xffffffffu, v, 2);
                    if (q == 0 && gid >= 0) g_pooled[(size_t)gid * 24 + cb * 4 + p] = v;
                } else {
                    if (gid >= 0) {
                        const int j0 = ((cb - 6) << 8) + p * 64 + q * 16;
                        #pragma unroll
                        for (int i = 0; i < 4; i++) {
                            float4 c4 = *(float4*)&stage[rr * 68 + q * 16 + i * 4];
                            *(float4*)(g_rlin + (size_t)gid * GJ + j0 + i * 4) = c4;
                        }
                    }
                }
                __syncthreads();
            }
        }

        gridbar();

        // ---------------- phase 2: gates + activations (one row per warp) ----
        for (int r2 = blockIdx.x * 16 + warp; r2 < R; r2 += ncta * 16) {
            const int gid = g_nodelist[s + r2];
            const int b = gid >> 9, t = gid & 511;
            const int par = nc[(b << 9) + t];
            const bool hasp = (t > 0 && par < t);
            const size_t pbase = hasp ? ((size_t)((b << 9) + par) << 9) : 0;
            const size_t ubase = (size_t)gid * GJ;
            const size_t obase = (size_t)gid << 9;

            float pl[24];
            {
                const float4* pp = (const float4*)(g_pooled + (size_t)gid * 24);
                #pragma unroll
                for (int i = 0; i < 6; i++) {
                    float4 qv = pp[i];
                    pl[i * 4] = qv.x; pl[i * 4 + 1] = qv.y; pl[i * 4 + 2] = qv.z; pl[i * 4 + 3] = qv.w;
                }
            }

            #pragma unroll
            for (int ch = 0; ch < 4; ch++) {
                const int h = ch * 128 + lane * 4;
                float gate[3][4];
                #pragma unroll
                for (int gg = 0; gg < 3; gg++) {
                    float4 u4 = *(const float4*)(g_Ubuf + ubase + (gg << 9) + h);
                    float4 r4 = *(const float4*)(g_rlin + ubase + (gg << 9) + h);
                    gate[gg][0] = u4.x + r4.x; gate[gg][1] = u4.y + r4.y;
                    gate[gg][2] = u4.z + r4.z; gate[gg][3] = u4.w + r4.w;
                    #pragma unroll
                    for (int j = 0; j < 4; j++) {
                        const float* wop = wo + ((size_t)(gg << 9) + h + j) * 8;
                        float4 w0 = *(const float4*)(wop);
                        float4 w1 = *(const float4*)(wop + 4);
                        gate[gg][j] += pl[(gg << 3) + 0] * w0.x + pl[(gg << 3) + 1] * w0.y
                                     + pl[(gg << 3) + 2] * w0.z + pl[(gg << 3) + 3] * w0.w
                                     + pl[(gg << 3) + 4] * w1.x + pl[(gg << 3) + 5] * w1.y
                                     + pl[(gg << 3) + 6] * w1.z + pl[(gg << 3) + 7] * w1.w;
                    }
                }
                float4 pc4 = hasp ? *(const float4*)(g_cbuf + pbase + h)
                                  : make_float4(0.f, 0.f, 0.f, 0.f);
                float pcv[4] = {pc4.x, pc4.y, pc4.z, pc4.w};
                float cv[4], hv[4];
                #pragma unroll
                for (int j = 0; j < 4; j++) {
                    const float f = 1.f / (1.f + expf(-gate[0][j]));
                    const float o = 1.f / (1.f + expf(-gate[1][j]));
                    const float z = tanhf(gate[2][j]);
                    const float c = pcv[j] * f + (1.f - f) * z;
                    cv[j] = c;
                    hv[j] = o * tanhf(c);
                }
                *(float4*)(g_cbuf + obase + h) = make_float4(cv[0], cv[1], cv[2], cv[3]);
                *(float4*)(out + obase + h)    = make_float4(hv[0], hv[1], hv[2], hv[3]);
                __half2* hd = (__half2*)(g_hH + obase + h);
                hd[0] = __floats2half2_rn(hv[0], hv[1]);
                hd[1] = __floats2half2_rn(hv[2], hv[3]);
            }
        }

        gridbar();
    }
}

// ---------------------------- launch ----------------------------------------
extern "C" void kernel_launch(void* const* d_in, const int* in_sizes, int n_in,
                              void* d_out, int out_size)
{
    (void)in_sizes; (void)n_in; (void)out_size;
    const float* emb  = (const float*)d_in[0];
    const int*   nc   = (const int*)d_in[1];
    // d_in[2] = node_mask (unused by reference)
    const float* wl   = (const float*)d_in[3];
    const float* wr   = (const float*)d_in[4];
    const float* wo   = (const float*)d_in[5];
    const float* ul   = (const float*)d_in[6];
    const float* ur   = (const float*)d_in[7];
    const float* bias = (const float*)d_in[8];
    float* out = (float*)d_out;

    // launch order: conv(0), depth(1), gemm(2), scan(3) — profiler slot = 3
    {
        const size_t nq = (size_t)MROWS * 512 / 4 + 4 * (NWELEM / 4);
        const int nb = (int)((nq + 255) / 256);
        conv_all<<<nb, 256>>>(emb, ul, wl, wr, ur);        // 0
    }
    build_depth<<<128, 32>>>(nc);                           // 1

    dim3 gp(GJ / 256, MROWS / 128, 2);                      // (6, 512, 2)
    gemm_pre<<<gp, 512>>>(bias);                            // 2

    scan_levels<<<NCTA, 512>>>(out, nc, wo);                // 3
}

// round 9
// speedup vs baseline: 1.0257x; 1.0257x over previous
#include <cuda_runtime.h>
#include <cuda_fp16.h>
#include <math.h>

// Problem constants
#define Bsz   128
#define Nn    512
#define GJ    1536          // 3*512 gate columns
#define MROWS (Bsz*Nn)      // 65536
#define NCTA  148           // persistent grid (1 CTA/SM guaranteed resident)
#define NWELEM 786432       // elements per weight matrix (1536*512)

// ---------------- device scratch (allocation-free) ---------------------------
__device__ float  g_Ubuf[(size_t)MROWS * GJ];   // emb@ul^T + bias (fp32)
__device__ __half g_LWH [(size_t)MROWS * GJ];   // emb@wl^T (fp16)
__device__ __half g_rlinH[(size_t)MROWS * GJ];  // ph@ur^T (fp16)
__device__ float  g_cbuf[(size_t)MROWS * 512];  // cell state
__device__ float  g_pooled[(size_t)MROWS * 24]; // pooled bilinear
__device__ __half g_embH[(size_t)MROWS * 512];  // fp16 emb
__device__ __half g_hH  [(size_t)MROWS * 512];  // fp16 h (scan A operand)
__device__ __half g_wH  [4 * NWELEM];           // fp16 weights: ul, wl, wr, ur
__device__ __half g_zeroH[512];                 // zero row

__device__ int g_level[MROWS];
__device__ int g_lcount[512];
__device__ int g_lstart[513];
__device__ int g_lcur[512];
__device__ int g_nodelist[MROWS];
__device__ int g_maxlev;

__device__ unsigned g_gcnt = 0;
__device__ unsigned g_ggen = 0;

// ---------------- mma / cp.async helpers -------------------------------------
__device__ __forceinline__ void mma16(float* c, const unsigned* a, const unsigned* b) {
    asm volatile(
        "mma.sync.aligned.m16n8k16.row.col.f32.f16.f16.f32 "
        "{%0,%1,%2,%3},{%4,%5,%6,%7},{%8,%9},{%0,%1,%2,%3};"
        : "+f"(c[0]), "+f"(c[1]), "+f"(c[2]), "+f"(c[3])
        : "r"(a[0]), "r"(a[1]), "r"(a[2]), "r"(a[3]), "r"(b[0]), "r"(b[1]));
}
__device__ __forceinline__ void cpa16(unsigned dst, const void* src) {
    asm volatile("cp.async.cg.shared.global [%0], [%1], 16;" :: "r"(dst), "l"(src));
}
#define CP_COMMIT() asm volatile("cp.async.commit_group;")
#define CP_WAIT1()  asm volatile("cp.async.wait_group 1;")

__device__ __forceinline__ unsigned ldh2(const __half* p) {
    return *(const unsigned*)p;
}

// ---------------- fp32 -> fp16 conversion (one pass, all GEMM inputs) --------
__global__ void conv_all(const float* __restrict__ emb,
                         const float* __restrict__ ul, const float* __restrict__ wl,
                         const float* __restrict__ wr, const float* __restrict__ ur)
{
    const size_t NE = (size_t)MROWS * 512 / 4;   // emb quarters
    const size_t NW = NWELEM / 4;                // weight quarters
    size_t i = (size_t)blockIdx.x * 256 + threadIdx.x;
    const float* src; __half* dst; size_t q;
    if (i < NE) { src = emb; dst = g_embH; q = i; }
    else {
        size_t j = i - NE;
        if (j >= 4 * NW) return;
        int w = (int)(j / NW); q = j % NW;
        src = (w == 0) ? ul : (w == 1) ? wl : (w == 2) ? wr : ur;
        dst = g_wH + (size_t)w * NWELEM;
    }
    float4 v = ((const float4*)src)[q];
    __half2* d2 = (__half2*)(dst + q * 4);
    d2[0] = __floats2half2_rn(v.x, v.y);
    d2[1] = __floats2half2_rn(v.z, v.w);
}

// ---------------- level metadata --------------------------------------------
__global__ void build_depth(const int* __restrict__ nc) {
    __shared__ int spar[512];
    __shared__ unsigned short dep[512];
    const int b = blockIdx.x;
    for (int t = threadIdx.x; t < 512; t += 32) spar[t] = nc[b * 512 + t];
    __syncthreads();
    if (threadIdx.x == 0) {
        for (int t = 0; t < 512; t++) {
            int par = spar[t];
            dep[t] = (t > 0 && par < t) ? (unsigned short)(dep[par] + 1) : 0;
        }
    }
    __syncthreads();
    for (int t = threadIdx.x; t < 512; t += 32) {
        int lv = dep[t];
        g_level[b * 512 + t] = lv;
        atomicAdd(&g_lcount[lv], 1);
    }
}

// ---------------- precompute GEMM (fp16 mma + cp.async) ----------------------
// C[M x 1536] = embH @ W^T (+bias). z selects ul(->Ubuf fp32) / wl(->LWH fp16).
// BM=128, BN=128, BK=32, 3 stages, 256 threads (8 warps 2m x 4n), warp 64x32.
__global__ __launch_bounds__(256, 2) void gemm_pre(const float* __restrict__ bias)
{
    __shared__ __align__(16) __half HSM[30720];  // 3 x (A 128x40 + B 128x40)

    const int sel = blockIdx.z;

    const int tid = threadIdx.x, lane = tid & 31, warp = tid >> 5;
    const int wm = (warp & 1) * 64, wn = (warp >> 1) * 32;
    const int g = lane >> 2, cc2 = (lane & 3) * 2, cc = lane & 3;
    const int r0 = blockIdx.y * 128, c0 = blockIdx.x * 128;
    const __half* Ab = g_embH + (size_t)r0 * 512;
    const __half* Wb = g_wH + (size_t)sel * NWELEM + (size_t)c0 * 512;

    const int lrow = tid >> 1, lcol = (tid & 1) * 16;
    const unsigned sb = (unsigned)__cvta_generic_to_shared(HSM);

    auto issue = [&](int s, int kt) {
        const __half* as_ = Ab + (size_t)lrow * 512 + kt * 32 + lcol;
        const __half* bs_ = Wb + (size_t)lrow * 512 + kt * 32 + lcol;
        unsigned ad = sb + (unsigned)(s * 10240 + lrow * 40 + lcol) * 2u;
        unsigned bd = sb + (unsigned)(s * 10240 + 5120 + lrow * 40 + lcol) * 2u;
        cpa16(ad, as_); cpa16(ad + 16, as_ + 8);
        cpa16(bd, bs_); cpa16(bd + 16, bs_ + 8);
    };

    issue(0, 0); CP_COMMIT();
    issue(1, 1); CP_COMMIT();

    float acc[4][4][4];
    #pragma unroll
    for (int mt = 0; mt < 4; mt++)
        #pragma unroll
        for (int nt = 0; nt < 4; nt++)
            #pragma unroll
            for (int j = 0; j < 4; j++) acc[mt][nt][j] = 0.f;

    for (int kt = 0; kt < 16; kt++) {
        CP_WAIT1();
        __syncthreads();
        if (kt + 2 < 16) issue((kt + 2) % 3, kt + 2);
        CP_COMMIT();

        const __half* As = HSM + (kt % 3) * 10240;
        const __half* Bs = As + 5120;
        #pragma unroll
        for (int ks = 0; ks < 2; ks++) {
            const int k0 = ks * 16;
            unsigned af[4][4], bf[4][2];
            #pragma unroll
            for (int mt = 0; mt < 4; mt++) {
                const int rb = wm + mt * 16 + g;
                af[mt][0] = ldh2(&As[rb * 40 + k0 + cc2]);
                af[mt][1] = ldh2(&As[(rb + 8) * 40 + k0 + cc2]);
                af[mt][2] = ldh2(&As[rb * 40 + k0 + cc2 + 8]);
                af[mt][3] = ldh2(&As[(rb + 8) * 40 + k0 + cc2 + 8]);
            }
            #pragma unroll
            for (int nt = 0; nt < 4; nt++) {
                const int nb = wn + nt * 8 + g;
                bf[nt][0] = ldh2(&Bs[nb * 40 + k0 + cc2]);
                bf[nt][1] = ldh2(&Bs[nb * 40 + k0 + cc2 + 8]);
            }
            #pragma unroll
            for (int mt = 0; mt < 4; mt++)
                #pragma unroll
                for (int nt = 0; nt < 4; nt++) mma16(acc[mt][nt], af[mt], bf[nt]);
        }
    }
    __syncthreads();

    // epilogue: 2 passes of 64 cols staged through smem (alias as float)
    float* stage = (float*)HSM;   // 128*68 floats = 34816B <= 61440B
    const int rr = tid >> 1, half = tid & 1;
    #pragma unroll
    for (int p = 0; p < 2; p++) {
        if ((warp >> 2) == p) {
            #pragma unroll
            for (int mt = 0; mt < 4; mt++)
                #pragma unroll
                for (int nt = 0; nt < 4; nt++) {
                    const int row = wm + mt * 16 + g, col = wn - p * 64 + nt * 8 + cc * 2;
                    *(float2*)&stage[row * 68 + col]       = make_float2(acc[mt][nt][0], acc[mt][nt][1]);
                    *(float2*)&stage[(row + 8) * 68 + col] = make_float2(acc[mt][nt][2], acc[mt][nt][3]);
                }
        }
        __syncthreads();
        const int cg = c0 + p * 64 + half * 32;
        #pragma unroll
        for (int i = 0; i < 8; i++) {
            float4 v = *(float4*)&stage[rr * 68 + half * 32 + i * 4];
            if (sel == 0) {
                v.x += bias[cg + i * 4];     v.y += bias[cg + i * 4 + 1];
                v.z += bias[cg + i * 4 + 2]; v.w += bias[cg + i * 4 + 3];
                *(float4*)(g_Ubuf + (size_t)(r0 + rr) * GJ + cg + i * 4) = v;
            } else {
                __half2* d = (__half2*)(g_LWH + (size_t)(r0 + rr) * GJ + cg + i * 4);
                d[0] = __floats2half2_rn(v.x, v.y);
                d[1] = __floats2half2_rn(v.z, v.w);
            }
        }
        __syncthreads();
    }
}

// ---------------- persistent level-scan kernel (fp16 mma + cp.async) ---------
// BM=128, BN=256, BK=32, 3 stages, 256 threads (8 warps 2m x 4n), warp 64x64.
__global__ __launch_bounds__(256) void scan_levels(
    float* __restrict__ out,
    const int* __restrict__ nc,
    const float* __restrict__ wo)    // (3, 512, 8)
{
    __shared__ __align__(16) __half HSM[46080];  // 3 x (A 128x40 + B 256x40)
    __shared__ int rowoff[128];
    __shared__ int rowgid[128];

    const int tid = threadIdx.x, lane = tid & 31, warp = tid >> 5;
    const int wm = (warp & 1) * 64, wn = (warp >> 1) * 64;
    const int g = lane >> 2, cc2 = (lane & 3) * 2, cc = lane & 3;
    const int arow = tid >> 1, acol = (tid & 1) * 16;
    const unsigned ncta = gridDim.x;
    const unsigned sb = (unsigned)__cvta_generic_to_shared(HSM);
    const __half* wrH = g_wH + 2 * (size_t)NWELEM;
    const __half* urH = g_wH + 3 * (size_t)NWELEM;

    const unsigned base = *(volatile unsigned*)&g_ggen;
    unsigned nbar = 0;

    auto gridbar = [&]() {
        nbar++;
        __syncthreads();
        if (tid == 0) {
            __threadfence();
            unsigned arrived = atomicAdd(&g_gcnt, 1u);
            if (arrived == ncta - 1u) {
                g_gcnt = 0;
                __threadfence();
                atomicAdd(&g_ggen, 1u);
            } else {
                while ((*(volatile unsigned*)&g_ggen) - base < nbar) { }
            }
            __threadfence();
        }
        __syncthreads();
    };

    // ---- prologue: prefix levels (CTA 0) then scatter ----
    if (blockIdx.x == 0 && tid == 0) {
        int sum = 0, mx = 0;
        for (int l = 0; l < 512; l++) {
            g_lstart[l] = sum;
            g_lcur[l]   = sum;
            int cnt = g_lcount[l];
            if (cnt > 0) mx = l;
            sum += cnt;
            g_lcount[l] = 0;
        }
        g_lstart[512] = sum;
        g_maxlev = mx;
    }
    gridbar();
    for (int i = blockIdx.x * 256 + tid; i < MROWS; i += ncta * 256) {
        int pos = atomicAdd(&g_lcur[g_level[i]], 1);
        g_nodelist[pos] = i;
    }
    gridbar();
    const int maxlev = *(volatile int*)&g_maxlev;

    for (int lev = 0; lev <= maxlev; lev++) {
        const int s = g_lstart[lev];
        const int R = g_lstart[lev + 1] - s;
        const int nrb = (R + 127) >> 7;
        const int units = nrb * 12;   // 3072/256 col blocks

        // ---------------- phase 1: recurrent GEMM + pooling ----------------
        for (int u = blockIdx.x; u < units; u += ncta) {
            const int rb = u / 12;
            const int cb = u - rb * 12;
            const int row0 = rb << 7;

            if (tid < 128) {
                int r = row0 + tid;
                int off = -1, gid = -1;
                if (r < R) {
                    gid = g_nodelist[s + r];
                    int b = gid >> 9, t = gid & 511;
                    int par = nc[(b << 9) + t];
                    if (t > 0 && par < t) off = ((b << 9) + par) << 9;
                }
                rowgid[tid] = gid;
                rowoff[tid] = off;
            }
            __syncthreads();

            const int aoff = rowoff[arow];
            const __half* abase = (aoff >= 0) ? (g_hH + (size_t)aoff) : g_zeroH;
            const __half* Wb = (cb < 6)
                ? (wrH + (size_t)cb * 131072)
                : (urH + (size_t)(cb - 6) * 131072);
            const __half* brow_ptr = Wb + (size_t)tid * 512;

            auto issue = [&](int st, int kt) {
                const __half* as_ = abase + kt * 32 + acol;
                unsigned ad = sb + (unsigned)(st * 15360 + arow * 40 + acol) * 2u;
                cpa16(ad, as_); cpa16(ad + 16, as_ + 8);
                const __half* bs_ = brow_ptr + kt * 32;
                unsigned bd = sb + (unsigned)(st * 15360 + 5120 + tid * 40) * 2u;
                cpa16(bd, bs_);      cpa16(bd + 16, bs_ + 8);
                cpa16(bd + 32, bs_ + 16); cpa16(bd + 48, bs_ + 24);
            };

            issue(0, 0); CP_COMMIT();
            issue(1, 1); CP_COMMIT();

            float acc[4][8][4];
            #pragma unroll
            for (int mt = 0; mt < 4; mt++)
                #pragma unroll
                for (int nt = 0; nt < 8; nt++)
                    #pragma unroll
                    for (int j = 0; j < 4; j++) acc[mt][nt][j] = 0.f;

            for (int kt = 0; kt < 16; kt++) {
                CP_WAIT1();
                __syncthreads();
                if (kt + 2 < 16) issue((kt + 2) % 3, kt + 2);
                CP_COMMIT();

                const __half* As = HSM + (kt % 3) * 15360;
                const __half* Bs = As + 5120;
                #pragma unroll
                for (int ks = 0; ks < 2; ks++) {
                    const int k0 = ks * 16;
                    unsigned af[4][4], bf[8][2];
                    #pragma unroll
                    for (int mt = 0; mt < 4; mt++) {
                        const int rb2 = wm + mt * 16 + g;
                        af[mt][0] = ldh2(&As[rb2 * 40 + k0 + cc2]);
                        af[mt][1] = ldh2(&As[(rb2 + 8) * 40 + k0 + cc2]);
                        af[mt][2] = ldh2(&As[rb2 * 40 + k0 + cc2 + 8]);
                        af[mt][3] = ldh2(&As[(rb2 + 8) * 40 + k0 + cc2 + 8]);
                    }
                    #pragma unroll
                    for (int nt = 0; nt < 8; nt++) {
                        const int nb2 = wn + nt * 8 + g;
                        bf[nt][0] = ldh2(&Bs[nb2 * 40 + k0 + cc2]);
                        bf[nt][1] = ldh2(&Bs[nb2 * 40 + k0 + cc2 + 8]);
                    }
                    #pragma unroll
                    for (int mt = 0; mt < 4; mt++)
                        #pragma unroll
                        for (int nt = 0; nt < 8; nt++) mma16(acc[mt][nt], af[mt], bf[nt]);
                }
            }
            __syncthreads();

            // epilogue: 4 passes of 64 cols through stage (alias SM as float)
            float* stage = (float*)HSM;
            const int rr = tid >> 1, half = tid & 1;
            const int gid = rowgid[rr];
            #pragma unroll
            for (int p = 0; p < 4; p++) {
                if ((warp >> 1) == p) {
                    #pragma unroll
                    for (int mt = 0; mt < 4; mt++)
                        #pragma unroll
                        for (int nt = 0; nt < 8; nt++) {
                            const int row = wm + mt * 16 + g, col = nt * 8 + cc * 2;
                            *(float2*)&stage[row * 68 + col]       = make_float2(acc[mt][nt][0], acc[mt][nt][1]);
                            *(float2*)&stage[(row + 8) * 68 + col] = make_float2(acc[mt][nt][2], acc[mt][nt][3]);
                        }
                }
                __syncthreads();

                if (cb < 6) {
                    // bilinear pooling: this 64-col slab = pool group cb*4+p
                    float v = 0.f;
                    if (gid >= 0) {
                        const __half* lwp = g_LWH + (size_t)gid * GJ + (cb << 8) + p * 64 + half * 32;
                        #pragma unroll
                        for (int i = 0; i < 4; i++) {
                            uint4 u = *(const uint4*)(lwp + i * 8);
                            float2 f0 = __half22float2(*(__half2*)&u.x);
                            float2 f1 = __half22float2(*(__half2*)&u.y);
                            float2 f2 = __half22float2(*(__half2*)&u.z);
                            float2 f3 = __half22float2(*(__half2*)&u.w);
                            float4 c4a = *(float4*)&stage[rr * 68 + half * 32 + i * 8];
                            float4 c4b = *(float4*)&stage[rr * 68 + half * 32 + i * 8 + 4];
                            v += c4a.x * f0.x + c4a.y * f0.y + c4a.z * f1.x + c4a.w * f1.y
                               + c4b.x * f2.x + c4b.y * f2.y + c4b.z * f3.x + c4b.w * f3.y;
                        }
                    }
                    v += __shfl_xor_sync(0xffffffffu, v, 1);
                    if (half == 0 && gid >= 0) g_pooled[(size_t)gid * 24 + cb * 4 + p] = v;
                } else {
                    if (gid >= 0) {
                        const int j0 = ((cb - 6) << 8) + p * 64 + half * 32;
                        #pragma unroll
                        for (int i = 0; i < 8; i++) {
                            float4 c4 = *(float4*)&stage[rr * 68 + half * 32 + i * 4];
                            __half2* d = (__half2*)(g_rlinH + (size_t)gid * GJ + j0 + i * 4);
                            d[0] = __floats2half2_rn(c4.x, c4.y);
                            d[1] = __floats2half2_rn(c4.z, c4.w);
                        }
                    }
                }
                __syncthreads();
            }
        }

        gridbar();

        // ---------------- phase 2: gates + activations (one row per warp) ----
        for (int r2 = blockIdx.x * 8 + warp; r2 < R; r2 += ncta * 8) {
            const int gid = g_nodelist[s + r2];
            const int b = gid >> 9, t = gid & 511;
            const int par = nc[(b << 9) + t];
            const bool hasp = (t > 0 && par < t);
            const size_t pbase = hasp ? ((size_t)((b << 9) + par) << 9) : 0;
            const size_t ubase = (size_t)gid * GJ;
            const size_t obase = (size_t)gid << 9;

            float pl[24];
            {
                const float4* pp = (const float4*)(g_pooled + (size_t)gid * 24);
                #pragma unroll
                for (int i = 0; i < 6; i++) {
                    float4 qv = pp[i];
                    pl[i * 4] = qv.x; pl[i * 4 + 1] = qv.y; pl[i * 4 + 2] = qv.z; pl[i * 4 + 3] = qv.w;
                }
            }

            #pragma unroll
            for (int ch = 0; ch < 4; ch++) {
                const int h = ch * 128 + lane * 4;
                float gate[3][4];
                #pragma unroll
                for (int gg = 0; gg < 3; gg++) {
                    float4 u4 = *(const float4*)(g_Ubuf + ubase + (gg << 9) + h);
                    uint2 ru = *(const uint2*)(g_rlinH + ubase + (gg << 9) + h);
                    float2 ra = __half22float2(*(__half2*)&ru.x);
                    float2 rb2 = __half22float2(*(__half2*)&ru.y);
                    gate[gg][0] = u4.x + ra.x;  gate[gg][1] = u4.y + ra.y;
                    gate[gg][2] = u4.z + rb2.x; gate[gg][3] = u4.w + rb2.y;
                    #pragma unroll
                    for (int j = 0; j < 4; j++) {
                        const float* wop = wo + ((size_t)(gg << 9) + h + j) * 8;
                        float4 w0 = *(const float4*)(wop);
                        float4 w1 = *(const float4*)(wop + 4);
                        gate[gg][j] += pl[(gg << 3) + 0] * w0.x + pl[(gg << 3) + 1] * w0.y
                                     + pl[(gg << 3) + 2] * w0.z + pl[(gg << 3) + 3] * w0.w
                                     + pl[(gg << 3) + 4] * w1.x + pl[(gg << 3) + 5] * w1.y
                                     + pl[(gg << 3) + 6] * w1.z + pl[(gg << 3) + 7] * w1.w;
                    }
                }
                float4 pc4 = hasp ? *(const float4*)(g_cbuf + pbase + h)
                                  : make_float4(0.f, 0.f, 0.f, 0.f);
                float pcv[4] = {pc4.x, pc4.y, pc4.z, pc4.w};
                float cv[4], hv[4];
                #pragma unroll
                for (int j = 0; j < 4; j++) {
                    const float f = 1.f / (1.f + expf(-gate[0][j]));
                    const float o = 1.f / (1.f + expf(-gate[1][j]));
                    const float z = tanhf(gate[2][j]);
                    const float c = pcv[j] * f + (1.f - f) * z;
                    cv[j] = c;
                    hv[j] = o * tanhf(c);
                }
                *(float4*)(g_cbuf + obase + h) = make_float4(cv[0], cv[1], cv[2], cv[3]);
                *(float4*)(out + obase + h)    = make_float4(hv[0], hv[1], hv[2], hv[3]);
                __half2* hd = (__half2*)(g_hH + obase + h);
                hd[0] = __floats2half2_rn(hv[0], hv[1]);
                hd[1] = __floats2half2_rn(hv[2], hv[3]);
            }
        }

        gridbar();
    }
}

// ---------------------------- launch ----------------------------------------
extern "C" void kernel_launch(void* const* d_in, const int* in_sizes, int n_in,
                              void* d_out, int out_size)
{
    (void)in_sizes; (void)n_in; (void)out_size;
    const float* emb  = (const float*)d_in[0];
    const int*   nc   = (const int*)d_in[1];
    // d_in[2] = node_mask (unused by reference)
    const float* wl   = (const float*)d_in[3];
    const float* wr   = (const float*)d_in[4];
    const float* wo   = (const float*)d_in[5];
    const float* ul   = (const float*)d_in[6];
    const float* ur   = (const float*)d_in[7];
    const float* bias = (const float*)d_in[8];
    float* out = (float*)d_out;

    // launch order: conv(0), depth(1), gemm(2), scan(3)
    {
        const size_t nq = (size_t)MROWS * 512 / 4 + 4 * (NWELEM / 4);
        const int nb = (int)((nq + 255) / 256);
        conv_all<<<nb, 256>>>(emb, ul, wl, wr, ur);        // 0
    }
    build_depth<<<128, 32>>>(nc);                           // 1

    dim3 gp(GJ / 128, MROWS / 128, 2);                      // (12, 512, 2)
    gemm_pre<<<gp, 256>>>(bias);                            // 2

    scan_levels<<<NCTA, 256>>>(out, nc, wo);                // 3
}

// round 10
// speedup vs baseline: 1.0943x; 1.0670x over previous
#include <cuda_runtime.h>
#include <cuda_fp16.h>
#include <math.h>

// Problem constants
#define Bsz   128
#define Nn    512
#define GJ    1536          // 3*512 gate columns
#define MROWS (Bsz*Nn)      // 65536
#define NCTA  148           // persistent grid (1 CTA/SM guaranteed resident)
#define NWELEM 786432       // elements per weight matrix (1536*512)

// ---------------- device scratch (allocation-free) ---------------------------
__device__ float  g_Ubuf[(size_t)MROWS * GJ];   // emb@ul^T + bias (fp32)
__device__ __half g_LWH [(size_t)MROWS * GJ];   // emb@wl^T (fp16)
__device__ __half g_rlinH[(size_t)MROWS * GJ];  // ph@ur^T (fp16)
__device__ float  g_cbuf[(size_t)MROWS * 512];  // cell state
__device__ float  g_pooled[(size_t)MROWS * 24]; // pooled bilinear
__device__ __half g_embH[(size_t)MROWS * 512];  // fp16 emb
__device__ __half g_hH  [(size_t)MROWS * 512];  // fp16 h (scan A operand)
__device__ __half g_wH  [4 * NWELEM];           // fp16 weights: ul, wl, wr, ur
__device__ __half g_zeroH[512];                 // zero row

__device__ int g_level[MROWS];
__device__ int g_lcount[512];
__device__ int g_lstart[513];
__device__ int g_lcur[512];
__device__ int g_nodelist[MROWS];
__device__ int g_maxlev;

__device__ unsigned g_gcnt = 0;
__device__ unsigned g_ggen = 0;

// ---------------- mma / cp.async / ldmatrix helpers --------------------------
__device__ __forceinline__ void mma16(float* c, const unsigned* a, const unsigned* b) {
    asm volatile(
        "mma.sync.aligned.m16n8k16.row.col.f32.f16.f16.f32 "
        "{%0,%1,%2,%3},{%4,%5,%6,%7},{%8,%9},{%0,%1,%2,%3};"
        : "+f"(c[0]), "+f"(c[1]), "+f"(c[2]), "+f"(c[3])
        : "r"(a[0]), "r"(a[1]), "r"(a[2]), "r"(a[3]), "r"(b[0]), "r"(b[1]));
}
__device__ __forceinline__ void cpa16(unsigned dst, const void* src) {
    asm volatile("cp.async.cg.shared.global [%0], [%1], 16;" :: "r"(dst), "l"(src));
}
#define CP_COMMIT() asm volatile("cp.async.commit_group;")
#define CP_WAIT1()  asm volatile("cp.async.wait_group 1;")

__device__ __forceinline__ void ldsm4(unsigned* r, unsigned addr) {
    asm volatile("ldmatrix.sync.aligned.m8n8.x4.shared.b16 {%0,%1,%2,%3}, [%4];"
        : "=r"(r[0]), "=r"(r[1]), "=r"(r[2]), "=r"(r[3]) : "r"(addr));
}

// ---------------- fp32 -> fp16 conversion (one pass, all GEMM inputs) --------
__global__ void conv_all(const float* __restrict__ emb,
                         const float* __restrict__ ul, const float* __restrict__ wl,
                         const float* __restrict__ wr, const float* __restrict__ ur)
{
    const size_t NE = (size_t)MROWS * 512 / 4;   // emb quarters
    const size_t NW = NWELEM / 4;                // weight quarters
    size_t i = (size_t)blockIdx.x * 256 + threadIdx.x;
    const float* src; __half* dst; size_t q;
    if (i < NE) { src = emb; dst = g_embH; q = i; }
    else {
        size_t j = i - NE;
        if (j >= 4 * NW) return;
        int w = (int)(j / NW); q = j % NW;
        src = (w == 0) ? ul : (w == 1) ? wl : (w == 2) ? wr : ur;
        dst = g_wH + (size_t)w * NWELEM;
    }
    float4 v = ((const float4*)src)[q];
    __half2* d2 = (__half2*)(dst + q * 4);
    d2[0] = __floats2half2_rn(v.x, v.y);
    d2[1] = __floats2half2_rn(v.z, v.w);
}

// ---------------- level metadata --------------------------------------------
__global__ void build_depth(const int* __restrict__ nc) {
    __shared__ int spar[512];
    __shared__ unsigned short dep[512];
    const int b = blockIdx.x;
    for (int t = threadIdx.x; t < 512; t += 32) spar[t] = nc[b * 512 + t];
    __syncthreads();
    if (threadIdx.x == 0) {
        for (int t = 0; t < 512; t++) {
            int par = spar[t];
            dep[t] = (t > 0 && par < t) ? (unsigned short)(dep[par] + 1) : 0;
        }
    }
    __syncthreads();
    for (int t = threadIdx.x; t < 512; t += 32) {
        int lv = dep[t];
        g_level[b * 512 + t] = lv;
        atomicAdd(&g_lcount[lv], 1);
    }
}

// ---------------- precompute GEMM (fp16 mma + ldmatrix + cp.async) -----------
// C[M x 1536] = embH @ W^T (+bias). z selects ul(->Ubuf fp32) / wl(->LWH fp16).
// BM=128, BN=128, BK=32, 3 stages, 256 threads (8 warps 2m x 4n), warp 64x32.
__global__ __launch_bounds__(256, 2) void gemm_pre(const float* __restrict__ bias)
{
    __shared__ __align__(16) __half HSM[30720];  // 3 x (A 128x40 + B 128x40)

    const int sel = blockIdx.z;

    const int tid = threadIdx.x, lane = tid & 31, warp = tid >> 5;
    const int wm = (warp & 1) * 64, wn = (warp >> 1) * 32;
    const int g = lane >> 2, cc = lane & 3;
    const int r0 = blockIdx.y * 128, c0 = blockIdx.x * 128;
    const __half* Ab = g_embH + (size_t)r0 * 512;
    const __half* Wb = g_wH + (size_t)sel * NWELEM + (size_t)c0 * 512;

    const int lrow = tid >> 1, lcol = (tid & 1) * 16;
    const unsigned sb = (unsigned)__cvta_generic_to_shared(HSM);

    // ldmatrix per-lane offsets
    const int a_r = (lane & 7) + ((lane >> 3) & 1) * 8;
    const int a_k = ((lane >> 4) & 1) * 8;
    const int b_r = (lane & 7) + ((lane >> 4) & 1) * 8;
    const int b_k = ((lane >> 3) & 1) * 8;

    auto issue = [&](int s, int kt) {
        const __half* as_ = Ab + (size_t)lrow * 512 + kt * 32 + lcol;
        const __half* bs_ = Wb + (size_t)lrow * 512 + kt * 32 + lcol;
        unsigned ad = sb + (unsigned)(s * 10240 + lrow * 40 + lcol) * 2u;
        unsigned bd = sb + (unsigned)(s * 10240 + 5120 + lrow * 40 + lcol) * 2u;
        cpa16(ad, as_); cpa16(ad + 16, as_ + 8);
        cpa16(bd, bs_); cpa16(bd + 16, bs_ + 8);
    };

    issue(0, 0); CP_COMMIT();
    issue(1, 1); CP_COMMIT();

    float acc[4][4][4];
    #pragma unroll
    for (int mt = 0; mt < 4; mt++)
        #pragma unroll
        for (int nt = 0; nt < 4; nt++)
            #pragma unroll
            for (int j = 0; j < 4; j++) acc[mt][nt][j] = 0.f;

    for (int kt = 0; kt < 16; kt++) {
        CP_WAIT1();
        __syncthreads();
        if (kt + 2 < 16) issue((kt + 2) % 3, kt + 2);
        CP_COMMIT();

        const unsigned abase = sb + (unsigned)((kt % 3) * 20480);
        const unsigned bbase = abase + 10240u;
        #pragma unroll
        for (int ks = 0; ks < 2; ks++) {
            const int koff = ks * 32;   // bytes (16 halves)
            unsigned af[4][4], bf[4][2];
            #pragma unroll
            for (int mt = 0; mt < 4; mt++)
                ldsm4(af[mt], abase + (unsigned)(((wm + mt * 16 + a_r) * 40 + a_k) * 2 + koff));
            #pragma unroll
            for (int p2 = 0; p2 < 2; p2++) {
                unsigned tq[4];
                ldsm4(tq, bbase + (unsigned)(((wn + p2 * 16 + b_r) * 40 + b_k) * 2 + koff));
                bf[2 * p2][0] = tq[0]; bf[2 * p2][1] = tq[1];
                bf[2 * p2 + 1][0] = tq[2]; bf[2 * p2 + 1][1] = tq[3];
            }
            #pragma unroll
            for (int mt = 0; mt < 4; mt++)
                #pragma unroll
                for (int nt = 0; nt < 4; nt++) mma16(acc[mt][nt], af[mt], bf[nt]);
        }
    }
    __syncthreads();

    // epilogue: 2 passes of 64 cols staged through smem (alias as float)
    float* stage = (float*)HSM;   // 128*68 floats = 34816B <= 61440B
    const int rr = tid >> 1, half = tid & 1;
    #pragma unroll
    for (int p = 0; p < 2; p++) {
        if ((warp >> 2) == p) {
            #pragma unroll
            for (int mt = 0; mt < 4; mt++)
                #pragma unroll
                for (int nt = 0; nt < 4; nt++) {
                    const int row = wm + mt * 16 + g, col = wn - p * 64 + nt * 8 + cc * 2;
                    *(float2*)&stage[row * 68 + col]       = make_float2(acc[mt][nt][0], acc[mt][nt][1]);
                    *(float2*)&stage[(row + 8) * 68 + col] = make_float2(acc[mt][nt][2], acc[mt][nt][3]);
                }
        }
        __syncthreads();
        const int cg = c0 + p * 64 + half * 32;
        #pragma unroll
        for (int i = 0; i < 8; i++) {
            float4 v = *(float4*)&stage[rr * 68 + half * 32 + i * 4];
            if (sel == 0) {
                v.x += bias[cg + i * 4];     v.y += bias[cg + i * 4 + 1];
                v.z += bias[cg + i * 4 + 2]; v.w += bias[cg + i * 4 + 3];
                *(float4*)(g_Ubuf + (size_t)(r0 + rr) * GJ + cg + i * 4) = v;
            } else {
                __half2* d = (__half2*)(g_LWH + (size_t)(r0 + rr) * GJ + cg + i * 4);
                d[0] = __floats2half2_rn(v.x, v.y);
                d[1] = __floats2half2_rn(v.z, v.w);
            }
        }
        __syncthreads();
    }
}

// ---------------- persistent level-scan kernel (fp16 mma + ldmatrix) ---------
// BM=128, BN=256, BK=32, 3 stages, 256 threads (8 warps 2m x 4n), warp 64x64.
__global__ __launch_bounds__(256) void scan_levels(
    float* __restrict__ out,
    const int* __restrict__ nc,
    const float* __restrict__ wo)    // (3, 512, 8)
{
    __shared__ __align__(16) __half HSM[46080];  // 3 x (A 128x40 + B 256x40)
    __shared__ int rowoff[128];
    __shared__ int rowgid[128];

    const int tid = threadIdx.x, lane = tid & 31, warp = tid >> 5;
    const int wm = (warp & 1) * 64, wn = (warp >> 1) * 64;
    const int g = lane >> 2, cc = lane & 3;
    const int arow = tid >> 1, acol = (tid & 1) * 16;
    const unsigned ncta = gridDim.x;
    const unsigned sb = (unsigned)__cvta_generic_to_shared(HSM);
    const __half* wrH = g_wH + 2 * (size_t)NWELEM;
    const __half* urH = g_wH + 3 * (size_t)NWELEM;

    // ldmatrix per-lane offsets
    const int a_r = (lane & 7) + ((lane >> 3) & 1) * 8;
    const int a_k = ((lane >> 4) & 1) * 8;
    const int b_r = (lane & 7) + ((lane >> 4) & 1) * 8;
    const int b_k = ((lane >> 3) & 1) * 8;

    const unsigned base = *(volatile unsigned*)&g_ggen;
    unsigned nbar = 0;

    auto gridbar = [&]() {
        nbar++;
        __syncthreads();
        if (tid == 0) {
            __threadfence();
            unsigned arrived = atomicAdd(&g_gcnt, 1u);
            if (arrived == ncta - 1u) {
                g_gcnt = 0;
                __threadfence();
                atomicAdd(&g_ggen, 1u);
            } else {
                while ((*(volatile unsigned*)&g_ggen) - base < nbar) { }
            }
            __threadfence();
        }
        __syncthreads();
    };

    // ---- prologue: prefix levels (CTA 0) then scatter ----
    if (blockIdx.x == 0 && tid == 0) {
        int sum = 0, mx = 0;
        for (int l = 0; l < 512; l++) {
            g_lstart[l] = sum;
            g_lcur[l]   = sum;
            int cnt = g_lcount[l];
            if (cnt > 0) mx = l;
            sum += cnt;
            g_lcount[l] = 0;
        }
        g_lstart[512] = sum;
        g_maxlev = mx;
    }
    gridbar();
    for (int i = blockIdx.x * 256 + tid; i < MROWS; i += ncta * 256) {
        int pos = atomicAdd(&g_lcur[g_level[i]], 1);
        g_nodelist[pos] = i;
    }
    gridbar();
    const int maxlev = *(volatile int*)&g_maxlev;

    for (int lev = 0; lev <= maxlev; lev++) {
        const int s = g_lstart[lev];
        const int R = g_lstart[lev + 1] - s;
        const int nrb = (R + 127) >> 7;
        const int units = nrb * 12;   // 3072/256 col blocks

        // ---------------- phase 1: recurrent GEMM + pooling ----------------
        for (int u = blockIdx.x; u < units; u += ncta) {
            const int rb = u / 12;
            const int cb = u - rb * 12;
            const int row0 = rb << 7;

            if (tid < 128) {
                int r = row0 + tid;
                int off = -1, gid = -1;
                if (r < R) {
                    gid = g_nodelist[s + r];
                    int b = gid >> 9, t = gid & 511;
                    int par = nc[(b << 9) + t];
                    if (t > 0 && par < t) off = ((b << 9) + par) << 9;
                }
                rowgid[tid] = gid;
                rowoff[tid] = off;
            }
            __syncthreads();

            const int aoff = rowoff[arow];
            const __half* abase = (aoff >= 0) ? (g_hH + (size_t)aoff) : g_zeroH;
            const __half* Wb = (cb < 6)
                ? (wrH + (size_t)cb * 131072)
                : (urH + (size_t)(cb - 6) * 131072);
            const __half* brow_ptr = Wb + (size_t)tid * 512;

            auto issue = [&](int st, int kt) {
                const __half* as_ = abase + kt * 32 + acol;
                unsigned ad = sb + (unsigned)(st * 15360 + arow * 40 + acol) * 2u;
                cpa16(ad, as_); cpa16(ad + 16, as_ + 8);
                const __half* bs_ = brow_ptr + kt * 32;
                unsigned bd = sb + (unsigned)(st * 15360 + 5120 + tid * 40) * 2u;
                cpa16(bd, bs_);      cpa16(bd + 16, bs_ + 8);
                cpa16(bd + 32, bs_ + 16); cpa16(bd + 48, bs_ + 24);
            };

            issue(0, 0); CP_COMMIT();
            issue(1, 1); CP_COMMIT();

            float acc[4][8][4];
            #pragma unroll
            for (int mt = 0; mt < 4; mt++)
                #pragma unroll
                for (int nt = 0; nt < 8; nt++)
                    #pragma unroll
                    for (int j = 0; j < 4; j++) acc[mt][nt][j] = 0.f;

            for (int kt = 0; kt < 16; kt++) {
                CP_WAIT1();
                __syncthreads();
                if (kt + 2 < 16) issue((kt + 2) % 3, kt + 2);
                CP_COMMIT();

                const unsigned abse = sb + (unsigned)((kt % 3) * 30720);
                const unsigned bbse = abse + 10240u;
                #pragma unroll
                for (int ks = 0; ks < 2; ks++) {
                    const int koff = ks * 32;   // bytes
                    unsigned af[4][4], bf[8][2];
                    #pragma unroll
                    for (int mt = 0; mt < 4; mt++)
                        ldsm4(af[mt], abse + (unsigned)(((wm + mt * 16 + a_r) * 40 + a_k) * 2 + koff));
                    #pragma unroll
                    for (int p2 = 0; p2 < 4; p2++) {
                        unsigned tq[4];
                        ldsm4(tq, bbse + (unsigned)(((wn + p2 * 16 + b_r) * 40 + b_k) * 2 + koff));
                        bf[2 * p2][0] = tq[0]; bf[2 * p2][1] = tq[1];
                        bf[2 * p2 + 1][0] = tq[2]; bf[2 * p2 + 1][1] = tq[3];
                    }
                    #pragma unroll
                    for (int mt = 0; mt < 4; mt++)
                        #pragma unroll
                        for (int nt = 0; nt < 8; nt++) mma16(acc[mt][nt], af[mt], bf[nt]);
                }
            }
            __syncthreads();

            // epilogue: 4 passes of 64 cols through stage (alias SM as float)
            float* stage = (float*)HSM;
            const int rr = tid >> 1, half = tid & 1;
            const int gid = rowgid[rr];
            #pragma unroll
            for (int p = 0; p < 4; p++) {
                if ((warp >> 1) == p) {
                    #pragma unroll
                    for (int mt = 0; mt < 4; mt++)
                        #pragma unroll
                        for (int nt = 0; nt < 8; nt++) {
                            const int row = wm + mt * 16 + g, col = nt * 8 + cc * 2;
                            *(float2*)&stage[row * 68 + col]       = make_float2(acc[mt][nt][0], acc[mt][nt][1]);
                            *(float2*)&stage[(row + 8) * 68 + col] = make_float2(acc[mt][nt][2], acc[mt][nt][3]);
                        }
                }
                __syncthreads();

                if (cb < 6) {
                    // bilinear pooling: this 64-col slab = pool group cb*4+p
                    float v = 0.f;
                    if (gid >= 0) {
                        const __half* lwp = g_LWH + (size_t)gid * GJ + (cb << 8) + p * 64 + half * 32;
                        #pragma unroll
                        for (int i = 0; i < 4; i++) {
                            uint4 u4 = *(const uint4*)(lwp + i * 8);
                            float2 f0 = __half22float2(*(__half2*)&u4.x);
                            float2 f1 = __half22float2(*(__half2*)&u4.y);
                            float2 f2 = __half22float2(*(__half2*)&u4.z);
                            float2 f3 = __half22float2(*(__half2*)&u4.w);
                            float4 c4a = *(float4*)&stage[rr * 68 + half * 32 + i * 8];
                            float4 c4b = *(float4*)&stage[rr * 68 + half * 32 + i * 8 + 4];
                            v += c4a.x * f0.x + c4a.y * f0.y + c4a.z * f1.x + c4a.w * f1.y
                               + c4b.x * f2.x + c4b.y * f2.y + c4b.z * f3.x + c4b.w * f3.y;
                        }
                    }
                    v += __shfl_xor_sync(0xffffffffu, v, 1);
                    if (half == 0 && gid >= 0) g_pooled[(size_t)gid * 24 + cb * 4 + p] = v;
                } else {
                    if (gid >= 0) {
                        const int j0 = ((cb - 6) << 8) + p * 64 + half * 32;
                        #pragma unroll
                        for (int i = 0; i < 8; i++) {
                            float4 c4 = *(float4*)&stage[rr * 68 + half * 32 + i * 4];
                            __half2* d = (__half2*)(g_rlinH + (size_t)gid * GJ + j0 + i * 4);
                            d[0] = __floats2half2_rn(c4.x, c4.y);
                            d[1] = __floats2half2_rn(c4.z, c4.w);
                        }
                    }
                }
                __syncthreads();
            }
        }

        gridbar();

        // ---------------- phase 2: gates + activations (one row per warp) ----
        for (int r2 = blockIdx.x * 8 + warp; r2 < R; r2 += ncta * 8) {
            const int gid = g_nodelist[s + r2];
            const int b = gid >> 9, t = gid & 511;
            const int par = nc[(b << 9) + t];
            const bool hasp = (t > 0 && par < t);
            const size_t pbase = hasp ? ((size_t)((b << 9) + par) << 9) : 0;
            const size_t ubase = (size_t)gid * GJ;
            const size_t obase = (size_t)gid << 9;

            float pl[24];
            {
                const float4* pp = (const float4*)(g_pooled + (size_t)gid * 24);
                #pragma unroll
                for (int i = 0; i < 6; i++) {
                    float4 qv = pp[i];
                    pl[i * 4] = qv.x; pl[i * 4 + 1] = qv.y; pl[i * 4 + 2] = qv.z; pl[i * 4 + 3] = qv.w;
                }
            }

            #pragma unroll
            for (int ch = 0; ch < 4; ch++) {
                const int h = ch * 128 + lane * 4;
                float gate[3][4];
                #pragma unroll
                for (int gg = 0; gg < 3; gg++) {
                    float4 u4 = *(const float4*)(g_Ubuf + ubase + (gg << 9) + h);
                    uint2 ru = *(const uint2*)(g_rlinH + ubase + (gg << 9) + h);
                    float2 ra = __half22float2(*(__half2*)&ru.x);
                    float2 rb2 = __half22float2(*(__half2*)&ru.y);
                    gate[gg][0] = u4.x + ra.x;  gate[gg][1] = u4.y + ra.y;
                    gate[gg][2] = u4.z + rb2.x; gate[gg][3] = u4.w + rb2.y;
                    #pragma unroll
                    for (int j = 0; j < 4; j++) {
                        const float* wop = wo + ((size_t)(gg << 9) + h + j) * 8;
                        float4 w0 = *(const float4*)(wop);
                        float4 w1 = *(const float4*)(wop + 4);
                        gate[gg][j] += pl[(gg << 3) + 0] * w0.x + pl[(gg << 3) + 1] * w0.y
                                     + pl[(gg << 3) + 2] * w0.z + pl[(gg << 3) + 3] * w0.w
                                     + pl[(gg << 3) + 4] * w1.x + pl[(gg << 3) + 5] * w1.y
                                     + pl[(gg << 3) + 6] * w1.z + pl[(gg << 3) + 7] * w1.w;
                    }
                }
                float4 pc4 = hasp ? *(const float4*)(g_cbuf + pbase + h)
                                  : make_float4(0.f, 0.f, 0.f, 0.f);
                float pcv[4] = {pc4.x, pc4.y, pc4.z, pc4.w};
                float cv[4], hv[4];
                #pragma unroll
                for (int j = 0; j < 4; j++) {
                    const float f = 1.f / (1.f + expf(-gate[0][j]));
                    const float o = 1.f / (1.f + expf(-gate[1][j]));
                    const float z = tanhf(gate[2][j]);
                    const float c = pcv[j] * f + (1.f - f) * z;
                    cv[j] = c;
                    hv[j] = o * tanhf(c);
                }
                *(float4*)(g_cbuf + obase + h) = make_float4(cv[0], cv[1], cv[2], cv[3]);
                *(float4*)(out + obase + h)    = make_float4(hv[0], hv[1], hv[2], hv[3]);
                __half2* hd = (__half2*)(g_hH + obase + h);
                hd[0] = __floats2half2_rn(hv[0], hv[1]);
                hd[1] = __floats2half2_rn(hv[2], hv[3]);
            }
        }

        gridbar();
    }
}

// ---------------------------- launch ----------------------------------------
extern "C" void kernel_launch(void* const* d_in, const int* in_sizes, int n_in,
                              void* d_out, int out_size)
{
    (void)in_sizes; (void)n_in; (void)out_size;
    const float* emb  = (const float*)d_in[0];
    const int*   nc   = (const int*)d_in[1];
    // d_in[2] = node_mask (unused by reference)
    const float* wl   = (const float*)d_in[3];
    const float* wr   = (const float*)d_in[4];
    const float* wo   = (const float*)d_in[5];
    const float* ul   = (const float*)d_in[6];
    const float* ur   = (const float*)d_in[7];
    const float* bias = (const float*)d_in[8];
    float* out = (float*)d_out;

    // launch order: conv(0), depth(1), gemm(2), scan(3)
    {
        const size_t nq = (size_t)MROWS * 512 / 4 + 4 * (NWELEM / 4);
        const int nb = (int)((nq + 255) / 256);
        conv_all<<<nb, 256>>>(emb, ul, wl, wr, ur);        // 0
    }
    build_depth<<<128, 32>>>(nc);                           // 1

    dim3 gp(GJ / 128, MROWS / 128, 2);                      // (12, 512, 2)
    gemm_pre<<<gp, 256>>>(bias);                            // 2

    scan_levels<<<NCTA, 256>>>(out, nc, wo);                // 3
}